// round 1
// baseline (speedup 1.0000x reference)
#include <cuda_runtime.h>
#include <math.h>

// Problem constants (B=4, L=4096, D=1024)
#define BB 4
#define LL 4096
#define DD 1024
#define MM (BB * LL)      // 16384 rows
#define KDIM (2 * DD)     // 2048
#define BLD (BB * LL * DD)
#define NCHUNK 16
#define CHUNK 256         // NCHUNK * CHUNK == LL

// scratch for chunk sums (no cudaMalloc allowed)
__device__ float g_sums[BB * NCHUNK * DD];

// ---------------- Pass A: per-chunk column sums ----------------
__global__ void scan_pass_a(const float* __restrict__ X) {
    int d = blockIdx.x * 256 + threadIdx.x;   // 0..1023
    int c = blockIdx.y;                        // chunk
    int b = blockIdx.z;                        // batch
    const float* p = X + ((size_t)(b * LL + c * CHUNK)) * DD + d;
    float s = 0.f;
#pragma unroll 8
    for (int i = 0; i < CHUNK; ++i) s += p[(size_t)i * DD];
    g_sums[(b * NCHUNK + c) * DD + d] = s;
}

// ---------------- Pass B: exclusive scan of chunk sums ----------------
__global__ void scan_pass_b() {
    int idx = blockIdx.x * 256 + threadIdx.x;  // 0..4095
    int b = idx >> 10;
    int d = idx & 1023;
    float run = 0.f;
#pragma unroll
    for (int c = 0; c < NCHUNK; ++c) {
        int off = (b * NCHUNK + c) * DD + d;
        float t = g_sums[off];
        g_sums[off] = run;
        run += t;
    }
}

// ---------------- Pass C: prefix mean, written to d_out second half ----------------
__global__ void scan_pass_c(const float* __restrict__ X, float* __restrict__ AVG) {
    int d = blockIdx.x * 256 + threadIdx.x;
    int c = blockIdx.y;
    int b = blockIdx.z;
    size_t base = ((size_t)(b * LL + c * CHUNK)) * DD + d;
    float run = g_sums[(b * NCHUNK + c) * DD + d];
    int l0 = c * CHUNK;
#pragma unroll 4
    for (int i = 0; i < CHUNK; ++i) {
        run += X[base + (size_t)i * DD];
        AVG[base + (size_t)i * DD] = run / (float)(l0 + i + 1);
    }
}

// ---------------- Fused gating GEMM ----------------
// C[m, j] over a virtual 128-col block: column j maps to W row
//   e = nd0 + (j>>1) + ((j&1) * DD)     (even j -> input gate, odd j -> forget gate)
// so each thread holds complete (ig, fg) pairs for its d's and the sigmoid
// gating epilogue is register-local.
__global__ __launch_bounds__(256, 1) void gemm_gate(
    const float* __restrict__ X, const float* __restrict__ AVG,
    const float* __restrict__ W, const float* __restrict__ bias,
    float* __restrict__ OUT)
{
    __shared__ __align__(16) float As[2][8][128];
    __shared__ __align__(16) float Bs[2][8][128];

    const int tid = threadIdx.x;          // 256 threads
    const int m0  = blockIdx.y * 128;     // row tile
    const int nd0 = blockIdx.x * 64;      // 64 d's -> 128 gate columns

    // ---- load mapping: one float4 of A and one of B per thread per k-tile
    const int lrow = tid >> 1;            // 0..127
    const int lkq  = tid & 1;             // which float4 inside the 8-wide k slab
    const int j    = lrow;                // B column id 0..127
    const int e    = nd0 + (j >> 1) + ((j & 1) << 10);  // W row
    const float* Wrow = W + (size_t)e * KDIM + lkq * 4;
    const size_t arow = (size_t)(m0 + lrow) * DD + lkq * 4;

    const int tx = tid & 15;              // 0..15 -> columns
    const int ty = tid >> 4;              // 0..15 -> rows

    float acc[8][8];
#pragma unroll
    for (int r = 0; r < 8; ++r)
#pragma unroll
        for (int c = 0; c < 8; ++c) acc[r][c] = 0.f;

    const int NT = KDIM / 8;              // 256 k-tiles

    // prologue: tile 0 (k0 = 0 < DD, so source is X)
    {
        float4 a = *(const float4*)(X + arow);
        float4 b4 = *(const float4*)(Wrow);
        As[0][lkq * 4 + 0][lrow] = a.x;  As[0][lkq * 4 + 1][lrow] = a.y;
        As[0][lkq * 4 + 2][lrow] = a.z;  As[0][lkq * 4 + 3][lrow] = a.w;
        Bs[0][lkq * 4 + 0][lrow] = b4.x; Bs[0][lkq * 4 + 1][lrow] = b4.y;
        Bs[0][lkq * 4 + 2][lrow] = b4.z; Bs[0][lkq * 4 + 3][lrow] = b4.w;
    }
    __syncthreads();

    for (int kt = 0; kt < NT; ++kt) {
        const int buf = kt & 1;
        float4 an, bn;
        if (kt + 1 < NT) {
            const int k0 = (kt + 1) * 8;
            const float* Asrc = (k0 < DD) ? X : AVG;
            const int kc = (k0 < DD) ? k0 : (k0 - DD);
            an = *(const float4*)(Asrc + arow + kc);
            bn = *(const float4*)(Wrow + k0);
        }
#pragma unroll
        for (int k = 0; k < 8; ++k) {
            float4 a0 = *(const float4*)&As[buf][k][ty * 4];
            float4 a1 = *(const float4*)&As[buf][k][64 + ty * 4];
            float4 b0 = *(const float4*)&Bs[buf][k][tx * 4];
            float4 b1 = *(const float4*)&Bs[buf][k][64 + tx * 4];
            float ar[8] = {a0.x, a0.y, a0.z, a0.w, a1.x, a1.y, a1.z, a1.w};
            float br[8] = {b0.x, b0.y, b0.z, b0.w, b1.x, b1.y, b1.z, b1.w};
#pragma unroll
            for (int r = 0; r < 8; ++r)
#pragma unroll
                for (int c = 0; c < 8; ++c)
                    acc[r][c] = fmaf(ar[r], br[c], acc[r][c]);
        }
        if (kt + 1 < NT) {
            const int nb = (kt + 1) & 1;
            As[nb][lkq * 4 + 0][lrow] = an.x;  As[nb][lkq * 4 + 1][lrow] = an.y;
            As[nb][lkq * 4 + 2][lrow] = an.z;  As[nb][lkq * 4 + 3][lrow] = an.w;
            Bs[nb][lkq * 4 + 0][lrow] = bn.x;  Bs[nb][lkq * 4 + 1][lrow] = bn.y;
            Bs[nb][lkq * 4 + 2][lrow] = bn.z;  Bs[nb][lkq * 4 + 3][lrow] = bn.w;
        }
        __syncthreads();
    }

    // ---- epilogue: ig/fg pairs are adjacent columns in acc
    int dl[4];
    dl[0] = nd0 + tx * 2;
    dl[1] = nd0 + tx * 2 + 1;
    dl[2] = nd0 + 32 + tx * 2;
    dl[3] = nd0 + 32 + tx * 2 + 1;
    float bi[4], bf[4];
#pragma unroll
    for (int p = 0; p < 4; ++p) {
        bi[p] = bias[dl[p]];
        bf[p] = bias[DD + dl[p]];
    }

#pragma unroll
    for (int r = 0; r < 8; ++r) {
        const int m = m0 + ((r < 4) ? (ty * 4 + r) : (64 + ty * 4 + (r - 4)));
        const size_t rowoff = (size_t)m * DD;
#pragma unroll
        for (int p = 0; p < 4; ++p) {
            const int c0 = (p < 2) ? (p * 2) : (4 + (p - 2) * 2);
            const float ig = acc[r][c0]     + bi[p];
            const float fg = acc[r][c0 + 1] + bf[p];
            const float xv = X[rowoff + dl[p]];
            const float av = AVG[rowoff + dl[p]];
            const float si = 1.f / (1.f + __expf(-ig));
            const float sf = 1.f / (1.f + __expf(-fg));
            OUT[rowoff + dl[p]] = si * xv + sf * av;
        }
    }
}

extern "C" void kernel_launch(void* const* d_in, const int* in_sizes, int n_in,
                              void* d_out, int out_size) {
    const float* X    = (const float*)d_in[0];  // inputs [4,4096,1024]
    const float* W    = (const float*)d_in[1];  // W_gate [2048,2048]
    const float* bias = (const float*)d_in[2];  // b_gate [2048]
    float* OUT = (float*)d_out;                 // gating_outputs first
    float* AVG = OUT + BLD;                     // average_outputs second

    dim3 gScan(DD / 256, NCHUNK, BB);           // (4,16,4)
    scan_pass_a<<<gScan, 256>>>(X);
    scan_pass_b<<<16, 256>>>();
    scan_pass_c<<<gScan, 256>>>(X, AVG);

    dim3 gG(DD / 64, MM / 128);                 // (16,128)
    gemm_gate<<<gG, 256>>>(X, AVG, W, bias, OUT);
}

// round 3
// speedup vs baseline: 4.7845x; 4.7845x over previous
#include <cuda_runtime.h>
#include <cuda_fp16.h>
#include <cstdint>
#include <math.h>

// Problem constants (B=4, L=4096, D=1024)
#define BB 4
#define LL 4096
#define DD 1024
#define MM (BB * LL)      // 16384 rows
#define KDIM (2 * DD)     // 2048
#define BLD (BB * LL * DD)
#define NCHUNK 16
#define CHUNK 256

// GEMM tiling
#define BM 128
#define BN 128
#define BKC 64               // k per stage (64 fp16 = 128B rows)
#define ST 3                 // pipeline stages
#define NCHG (KDIM / BKC)    // 32 k-chunks
#define STAGE_BYTES 32768    // A 16KB + B 16KB

// ---- device scratch (no cudaMalloc allowed) ----
__device__ float g_sums[BB * NCHUNK * DD];
__device__ __align__(256) __half g_A16[(size_t)MM * KDIM];    // fp16 concat(X, AVG)
__device__ __align__(256) __half g_W16[(size_t)KDIM * KDIM];  // fp16 permuted W

// ---------------- helpers ----------------
__device__ __forceinline__ uint32_t smem_u32(const void* p) {
    uint32_t a;
    asm("{ .reg .u64 t; cvta.to.shared.u64 t, %1; cvt.u32.u64 %0, t; }" : "=r"(a) : "l"(p));
    return a;
}
__device__ __forceinline__ void cp16(uint32_t dst, const void* src) {
    asm volatile("cp.async.cg.shared.global [%0], [%1], 16;" :: "r"(dst), "l"(src));
}
__device__ __forceinline__ void cp_commit() {
    asm volatile("cp.async.commit_group;" ::: "memory");
}
template <int N>
__device__ __forceinline__ void cp_wait() {
    asm volatile("cp.async.wait_group %0;" :: "n"(N) : "memory");
}
__device__ __forceinline__ void ldsm4(uint32_t& r0, uint32_t& r1, uint32_t& r2,
                                      uint32_t& r3, uint32_t addr) {
    asm volatile("ldmatrix.sync.aligned.m8n8.x4.shared.b16 {%0,%1,%2,%3}, [%4];"
                 : "=r"(r0), "=r"(r1), "=r"(r2), "=r"(r3) : "r"(addr));
}
__device__ __forceinline__ void mma16816(float& c0, float& c1, float& c2, float& c3,
                                         uint32_t a0, uint32_t a1, uint32_t a2, uint32_t a3,
                                         uint32_t b0, uint32_t b1) {
    asm volatile(
        "mma.sync.aligned.m16n8k16.row.col.f32.f16.f16.f32 "
        "{%0,%1,%2,%3}, {%4,%5,%6,%7}, {%8,%9}, {%0,%1,%2,%3};"
        : "+f"(c0), "+f"(c1), "+f"(c2), "+f"(c3)
        : "r"(a0), "r"(a1), "r"(a2), "r"(a3), "r"(b0), "r"(b1));
}

// ---------------- Pass A: per-chunk column sums + fp16 X copy ----------------
__global__ void scan_pass_a(const float* __restrict__ X) {
    int d = blockIdx.x * 256 + threadIdx.x;
    int c = blockIdx.y;
    int b = blockIdx.z;
    size_t row0 = (size_t)(b * LL + c * CHUNK);
    const float* p = X + row0 * DD + d;
    float s = 0.f;
#pragma unroll 4
    for (int i = 0; i < CHUNK; ++i) {
        float v = p[(size_t)i * DD];
        s += v;
        g_A16[(row0 + i) * KDIM + d] = __float2half_rn(v);
    }
    g_sums[(b * NCHUNK + c) * DD + d] = s;
}

// ---------------- Pass B: exclusive scan of chunk sums ----------------
__global__ void scan_pass_b() {
    int idx = blockIdx.x * 256 + threadIdx.x;
    int b = idx >> 10;
    int d = idx & 1023;
    float run = 0.f;
#pragma unroll
    for (int c = 0; c < NCHUNK; ++c) {
        int off = (b * NCHUNK + c) * DD + d;
        float t = g_sums[off];
        g_sums[off] = run;
        run += t;
    }
}

// ---------------- Pass C: prefix mean -> AVG (exact fp32) + fp16 copy ----------------
__global__ void scan_pass_c(const float* __restrict__ X, float* __restrict__ AVG) {
    int d = blockIdx.x * 256 + threadIdx.x;
    int c = blockIdx.y;
    int b = blockIdx.z;
    size_t row0 = (size_t)(b * LL + c * CHUNK);
    size_t base = row0 * DD + d;
    float run = g_sums[(b * NCHUNK + c) * DD + d];
    int l0 = c * CHUNK;
#pragma unroll 4
    for (int i = 0; i < CHUNK; ++i) {
        run += X[base + (size_t)i * DD];
        float a = run / (float)(l0 + i + 1);
        AVG[base + (size_t)i * DD] = a;
        g_A16[(row0 + i) * KDIM + DD + d] = __float2half_rn(a);
    }
}

// ---------------- W conversion: permute + fp16 ----------------
// Wperm[j][k] = fp16(W[e(j)][k]),  e(j) = (j>>1) + (j&1)*1024
__global__ void conv_w(const float* __restrict__ W) {
    size_t idx = (size_t)blockIdx.x * 256 + threadIdx.x;
    int j = (int)(idx >> 11);
    int k = (int)(idx & 2047);
    int e = (j >> 1) + ((j & 1) << 10);
    g_W16[idx] = __float2half_rn(W[(size_t)e * KDIM + k]);
}

// ---------------- fp16 mma.sync GEMM + fused gating epilogue ----------------
// grid (16, 128): x = n-tile (128 permuted cols = 64 d), y = m-tile (128 rows)
__global__ __launch_bounds__(256, 2) void gemm_gate(
    const float* __restrict__ X, const float* __restrict__ bias,
    float* __restrict__ OUT)
{
    extern __shared__ __align__(1024) char smem[];
    const uint32_t sb = smem_u32(smem);
    const int tid = threadIdx.x;
    const int lane = tid & 31;
    const int wid = tid >> 5;            // 8 warps
    const int wm = wid & 1;              // 2 in m (64 each)
    const int wn = wid >> 1;             // 4 in n (32 each)
    const int m0 = blockIdx.y * BM;
    const int n0 = blockIdx.x * BN;
    const float* AVG = OUT + BLD;

    const __half* gA = g_A16 + (size_t)m0 * KDIM;
    const __half* gB = g_W16 + (size_t)n0 * KDIM;

    // ---- stage loader: 8 x cp.async(16B) per thread ----
    auto load_stage = [&](int s, int kt) {
        const uint32_t abase = sb + s * STAGE_BYTES;
        const uint32_t bbase = abase + 16384u;
        const __half* a = gA + kt * BKC;
        const __half* b = gB + kt * BKC;
#pragma unroll
        for (int i = 0; i < 4; ++i) {
            int lin = i * 256 + tid;          // 0..1023
            int row = lin >> 3;               // 0..127
            int ch  = lin & 7;                // 16B chunk within 128B row
            uint32_t off = (uint32_t)(row * 128 + ((ch ^ (row & 7)) << 4));
            cp16(abase + off, a + (size_t)row * KDIM + ch * 8);
            cp16(bbase + off, b + (size_t)row * KDIM + ch * 8);
        }
    };

    float acc[4][4][4];
#pragma unroll
    for (int i = 0; i < 4; ++i)
#pragma unroll
        for (int j = 0; j < 4; ++j)
#pragma unroll
            for (int v = 0; v < 4; ++v) acc[i][j][v] = 0.f;

    // prologue: prefetch ST-1 stages
    load_stage(0, 0); cp_commit();
    load_stage(1, 1); cp_commit();

    for (int kt = 0; kt < NCHG; ++kt) {
        cp_wait<ST - 2>();
        __syncthreads();
        if (kt + 2 < NCHG) load_stage((kt + 2) % ST, kt + 2);
        cp_commit();

        const int s = kt % ST;
        const uint32_t abase = sb + s * STAGE_BYTES;
        const uint32_t bbase = abase + 16384u;

#pragma unroll
        for (int kk = 0; kk < 4; ++kk) {
            uint32_t af[4][4];
#pragma unroll
            for (int i = 0; i < 4; ++i) {
                int row = wm * 64 + i * 16 + (lane & 15);
                int ch  = kk * 2 + (lane >> 4);
                ldsm4(af[i][0], af[i][1], af[i][2], af[i][3],
                      abase + (uint32_t)(row * 128 + ((ch ^ (row & 7)) << 4)));
            }
            uint32_t bf[2][4];
#pragma unroll
            for (int jn = 0; jn < 2; ++jn) {
                int row = wn * 32 + jn * 16 + (lane & 7) + ((lane >> 4) << 3);
                int ch  = kk * 2 + ((lane >> 3) & 1);
                ldsm4(bf[jn][0], bf[jn][1], bf[jn][2], bf[jn][3],
                      bbase + (uint32_t)(row * 128 + ((ch ^ (row & 7)) << 4)));
            }
#pragma unroll
            for (int i = 0; i < 4; ++i)
#pragma unroll
                for (int j = 0; j < 4; ++j) {
                    const int jn = j >> 1, p = j & 1;
                    mma16816(acc[i][j][0], acc[i][j][1], acc[i][j][2], acc[i][j][3],
                             af[i][0], af[i][1], af[i][2], af[i][3],
                             bf[jn][p * 2], bf[jn][p * 2 + 1]);
                }
        }
    }

    // ---- register-local gating epilogue ----
    // c-frag: c0 at (row=l/4, col=2(l%4)), c1 col+1, c2/c3 at row+8.
    // permuted col -> even = ig, odd = fg for d = col/2.
#pragma unroll
    for (int j = 0; j < 4; ++j) {
        const int d = ((n0 + wn * 32 + j * 8) >> 1) + (lane & 3);
        const float bi = __ldg(bias + d);
        const float bfv = __ldg(bias + DD + d);
#pragma unroll
        for (int i = 0; i < 4; ++i) {
            const int r0 = m0 + wm * 64 + i * 16 + (lane >> 2);
#pragma unroll
            for (int h = 0; h < 2; ++h) {
                const int m = r0 + h * 8;
                const size_t gi = (size_t)m * DD + d;
                const float ig = acc[i][j][h * 2]     + bi;
                const float fg = acc[i][j][h * 2 + 1] + bfv;
                const float x  = __ldg(X + gi);
                const float av = AVG[gi];
                OUT[gi] = x * (1.f / (1.f + __expf(-ig)))
                        + av * (1.f / (1.f + __expf(-fg)));
            }
        }
    }
}

extern "C" void kernel_launch(void* const* d_in, const int* in_sizes, int n_in,
                              void* d_out, int out_size) {
    const float* X    = (const float*)d_in[0];
    const float* W    = (const float*)d_in[1];
    const float* bias = (const float*)d_in[2];
    float* OUT = (float*)d_out;
    float* AVG = OUT + BLD;

    static int attr_set = 0;
    const int smem_bytes = ST * STAGE_BYTES;     // 98304
    if (!attr_set) {
        cudaFuncSetAttribute(gemm_gate, cudaFuncAttributeMaxDynamicSharedMemorySize, smem_bytes);
        attr_set = 1;
    }

    dim3 gScan(DD / 256, NCHUNK, BB);
    scan_pass_a<<<gScan, 256>>>(X);
    scan_pass_b<<<16, 256>>>();
    scan_pass_c<<<gScan, 256>>>(X, AVG);
    conv_w<<<(KDIM * KDIM) / 256, 256>>>(W);

    dim3 gG(KDIM / BN, MM / BM);                 // (16, 128)
    gemm_gate<<<gG, 256, smem_bytes>>>(X, bias, OUT);
}